// round 3
// baseline (speedup 1.0000x reference)
#include <cuda_runtime.h>
#include <math.h>

#define N_NODES 100000
#define E_EDGES 1200000
#define EPS 1e-5f

// -------- scratch (device globals; no allocation allowed) --------
__device__ float g_A[N_NODES * 64];     // ping-pong conv accumulator
__device__ float g_B[N_NODES * 64];     // h = (bn_elu(prev) or x) @ W
__device__ float g_C[N_NODES * 64];     // ping-pong conv accumulator
__device__ float g_dinv[N_NODES];
__device__ float g_norm[E_EDGES];
__device__ int   g_deg[N_NODES];
__device__ float g_stats[3][128];       // per-layer: [0..63] sum, [64..127] sumsq

// ----------------- degree / norm precompute -----------------
__global__ void k_deg_init(int* deg, int n) {
    int i = blockIdx.x * blockDim.x + threadIdx.x;
    if (i < n) deg[i] = 1;  // self loop
}

__global__ void k_deg_count(const int* __restrict__ dst, int* deg, int e) {
    int i = blockIdx.x * blockDim.x + threadIdx.x;
    if (i < e) atomicAdd(&deg[dst[i]], 1);
}

__global__ void k_dinv(const int* __restrict__ deg, float* dinv, int n) {
    int i = blockIdx.x * blockDim.x + threadIdx.x;
    if (i < n) dinv[i] = rsqrtf((float)deg[i]);
}

__global__ void k_norm(const int* __restrict__ src, const int* __restrict__ dst,
                       const float* __restrict__ dinv, float* norm, int e) {
    int i = blockIdx.x * blockDim.x + threadIdx.x;
    if (i < e) norm[i] = __ldg(&dinv[src[i]]) * __ldg(&dinv[dst[i]]);
}

// ----------------- layer-1 GEMM + self-loop init (+ zero stats[0]) -----------------
template <int FIN, int FOUT>
__global__ void k_gemm_init(const float* __restrict__ x, const float* __restrict__ W,
                            const float* __restrict__ b, const float* __restrict__ dinv,
                            float* __restrict__ h, float* __restrict__ outc,
                            float* __restrict__ stats_zero, int n) {
    __shared__ float sW[FIN * FOUT];
    __shared__ float sb[FOUT];
    for (int i = threadIdx.x; i < FIN * FOUT; i += blockDim.x) sW[i] = W[i];
    for (int i = threadIdx.x; i < FOUT; i += blockDim.x) sb[i] = b[i];
    if (blockIdx.x == 0 && threadIdx.x < 128) stats_zero[threadIdx.x] = 0.0f;
    __syncthreads();
    int node = blockIdx.x * blockDim.x + threadIdx.x;
    if (node >= n) return;
    float xv[FIN];
#pragma unroll
    for (int k = 0; k < FIN; k++) xv[k] = x[node * FIN + k];
    float di = dinv[node];
    float di2 = di * di;
#pragma unroll 4
    for (int j = 0; j < FOUT; j++) {
        float acc = 0.0f;
#pragma unroll
        for (int k = 0; k < FIN; k++) acc = fmaf(xv[k], sW[k * FOUT + j], acc);
        h[node * FOUT + j] = acc;
        outc[node * FOUT + j] = sb[j] + di2 * acc;
    }
}

// ----------------- fused relu+BN+ELU (of prev layer) + GEMM + self-loop init -----------------
// NOTE: c (input accumulator) and outc (output accumulator) MUST be different buffers.
template <int FIN, int FOUT>
__global__ void k_bn_gemm(const float* __restrict__ c, const float* __restrict__ stats_in,
                          const float* __restrict__ g, const float* __restrict__ bt,
                          const float* __restrict__ W, const float* __restrict__ b,
                          const float* __restrict__ dinv,
                          float* __restrict__ h, float* __restrict__ outc,
                          float* __restrict__ stats_zero, int n) {
    __shared__ float sW[FIN * FOUT];
    __shared__ float sb[FOUT];
    __shared__ float smean[FIN], sscale[FIN], sbt[FIN];  // scale = istd * gamma
    for (int i = threadIdx.x; i < FIN * FOUT; i += blockDim.x) sW[i] = W[i];
    for (int i = threadIdx.x; i < FOUT; i += blockDim.x) sb[i] = b[i];
    if (threadIdx.x < FIN) {
        int col = threadIdx.x;
        float inv_n = 1.0f / (float)n;
        float mean = stats_in[col] * inv_n;
        float var = stats_in[64 + col] * inv_n - mean * mean;
        smean[col] = mean;
        sscale[col] = rsqrtf(var + EPS) * g[col];
        sbt[col] = bt[col];
    }
    if (blockIdx.x == 0 && threadIdx.x < 128) stats_zero[threadIdx.x] = 0.0f;
    __syncthreads();
    int node = blockIdx.x * blockDim.x + threadIdx.x;
    if (node >= n) return;
    float xv[FIN];
#pragma unroll
    for (int k = 0; k < FIN; k++) {
        float v = fmaxf(c[node * FIN + k], 0.0f);           // relu
        float y = (v - smean[k]) * sscale[k] + sbt[k];      // bn
        xv[k] = (y > 0.0f) ? y : expm1f(y);                 // elu
    }
    float di = dinv[node];
    float di2 = di * di;
#pragma unroll 4
    for (int j = 0; j < FOUT; j++) {
        float acc = 0.0f;
#pragma unroll
        for (int k = 0; k < FIN; k++) acc = fmaf(xv[k], sW[k * FOUT + j], acc);
        h[node * FOUT + j] = acc;
        outc[node * FOUT + j] = sb[j] + di2 * acc;
    }
}

// ----------------- edge scatter (vector atomics) -----------------
template <int F>
__global__ void k_scatter(const float* __restrict__ h, const int* __restrict__ src,
                          const int* __restrict__ dst, const float* __restrict__ norm,
                          float* __restrict__ outc, int e) {
    constexpr int Q = F / 4;  // float4 chunks per edge
    int idx = blockIdx.x * blockDim.x + threadIdx.x;
    if (idx >= e * Q) return;
    int eidx = idx / Q;
    int q = idx - eidx * Q;
    int s = __ldg(&src[eidx]);
    int d = __ldg(&dst[eidx]);
    float nv = __ldg(&norm[eidx]);
    const float4 hv = *reinterpret_cast<const float4*>(h + (size_t)s * F + q * 4);
    float4 v = make_float4(hv.x * nv, hv.y * nv, hv.z * nv, hv.w * nv);
    atomicAdd(reinterpret_cast<float4*>(outc + (size_t)d * F + q * 4), v);
}

// ----------------- relu + per-feature sum/sumsq -----------------
template <int F>
__global__ void k_stats(const float* __restrict__ c, float* __restrict__ stats, int n) {
    __shared__ float ss[256];
    __shared__ float sq[256];
    int tid = threadIdx.x;
    long total = (long)n * F;
    long stride = (long)blockDim.x * gridDim.x;  // multiple of F (F divides 256)
    float s = 0.0f, s2 = 0.0f;
    for (long i = (long)blockIdx.x * blockDim.x + tid; i < total; i += stride) {
        float v = fmaxf(c[i], 0.0f);
        s += v;
        s2 = fmaf(v, v, s2);
    }
    ss[tid] = s;
    sq[tid] = s2;
    __syncthreads();
    for (int off = 128; off >= F; off >>= 1) {
        if (tid < off) {
            ss[tid] += ss[tid + off];
            sq[tid] += sq[tid + off];
        }
        __syncthreads();
    }
    if (tid < F) {
        atomicAdd(&stats[tid], ss[tid]);
        atomicAdd(&stats[64 + tid], sq[tid]);
    }
}

// ----------------- fused relu+BN+ELU + MLP + log_softmax -----------------
__global__ void __launch_bounds__(128)
k_mlp(const float* __restrict__ c, const float* __restrict__ stats_in,
      const float* __restrict__ g, const float* __restrict__ bt,
      const float* __restrict__ Wf1, const float* __restrict__ bf1,
      const float* __restrict__ Wf2, const float* __restrict__ bf2,
      const float* __restrict__ Wf3, const float* __restrict__ bf3,
      float* __restrict__ out, int n) {
    __shared__ float sW1[64 * 32], sb1[32];
    __shared__ float sW2[32 * 16], sb2[16];
    __shared__ float sW3[16 * 2], sb3[2];
    __shared__ float smean[64], sscale[64], sbt[64];
    for (int i = threadIdx.x; i < 64 * 32; i += blockDim.x) sW1[i] = Wf1[i];
    for (int i = threadIdx.x; i < 32 * 16; i += blockDim.x) sW2[i] = Wf2[i];
    for (int i = threadIdx.x; i < 32; i += blockDim.x) sW3[i] = Wf3[i];
    if (threadIdx.x < 32) sb1[threadIdx.x] = bf1[threadIdx.x];
    if (threadIdx.x < 16) sb2[threadIdx.x] = bf2[threadIdx.x];
    if (threadIdx.x < 2) sb3[threadIdx.x] = bf3[threadIdx.x];
    if (threadIdx.x < 64) {
        int col = threadIdx.x;
        float inv_n = 1.0f / (float)n;
        float mean = stats_in[col] * inv_n;
        float var = stats_in[64 + col] * inv_n - mean * mean;
        smean[col] = mean;
        sscale[col] = rsqrtf(var + EPS) * g[col];
        sbt[col] = bt[col];
    }
    __syncthreads();
    int node = blockIdx.x * blockDim.x + threadIdx.x;
    if (node >= n) return;

    float x[64];
    const float4* hp = reinterpret_cast<const float4*>(c + (size_t)node * 64);
#pragma unroll
    for (int k4 = 0; k4 < 16; k4++) {
        float4 v4 = hp[k4];
        float tmp[4] = {v4.x, v4.y, v4.z, v4.w};
#pragma unroll
        for (int j = 0; j < 4; j++) {
            int k = k4 * 4 + j;
            float v = fmaxf(tmp[j], 0.0f);
            float y = (v - smean[k]) * sscale[k] + sbt[k];
            x[k] = (y > 0.0f) ? y : expm1f(y);
        }
    }

    float t1[32];
#pragma unroll 4
    for (int j = 0; j < 32; j++) {
        float acc = sb1[j];
#pragma unroll
        for (int k = 0; k < 64; k++) acc = fmaf(x[k], sW1[k * 32 + j], acc);
        t1[j] = (acc > 0.0f) ? acc : expm1f(acc);
    }

    float t2[16];
#pragma unroll 4
    for (int j = 0; j < 16; j++) {
        float acc = sb2[j];
#pragma unroll
        for (int k = 0; k < 32; k++) acc = fmaf(t1[k], sW2[k * 16 + j], acc);
        t2[j] = (acc > 0.0f) ? acc : expm1f(acc);
    }

    float o0 = sb3[0], o1 = sb3[1];
#pragma unroll
    for (int k = 0; k < 16; k++) {
        o0 = fmaf(t2[k], sW3[k * 2 + 0], o0);
        o1 = fmaf(t2[k], sW3[k * 2 + 1], o1);
    }
    float m = fmaxf(o0, o1);
    float lse = m + logf(expf(o0 - m) + expf(o1 - m));
    out[node * 2 + 0] = o0 - lse;
    out[node * 2 + 1] = o1 - lse;
}

// ----------------- launch -----------------
extern "C" void kernel_launch(void* const* d_in, const int* in_sizes, int n_in,
                              void* d_out, int out_size) {
    const float* x   = (const float*)d_in[0];
    const int* eidx  = (const int*)d_in[1];
    const float* W1  = (const float*)d_in[2];
    const float* b1  = (const float*)d_in[3];
    const float* g1  = (const float*)d_in[4];
    const float* bt1 = (const float*)d_in[5];
    const float* W2  = (const float*)d_in[6];
    const float* b2  = (const float*)d_in[7];
    const float* g2  = (const float*)d_in[8];
    const float* bt2 = (const float*)d_in[9];
    const float* W3  = (const float*)d_in[10];
    const float* b3  = (const float*)d_in[11];
    const float* g3  = (const float*)d_in[12];
    const float* bt3 = (const float*)d_in[13];
    const float* Wf1 = (const float*)d_in[14];
    const float* bf1 = (const float*)d_in[15];
    const float* Wf2 = (const float*)d_in[16];
    const float* bf2 = (const float*)d_in[17];
    const float* Wf3 = (const float*)d_in[18];
    const float* bf3 = (const float*)d_in[19];
    float* out = (float*)d_out;

    const int n = in_sizes[0] / 4;
    const int e = in_sizes[1] / 2;
    const int* src = eidx;
    const int* dst = eidx + e;

    float *pA, *pB, *pC, *pDinv, *pNorm, *pStats;
    int* pDeg;
    cudaGetSymbolAddress((void**)&pA, g_A);
    cudaGetSymbolAddress((void**)&pB, g_B);
    cudaGetSymbolAddress((void**)&pC, g_C);
    cudaGetSymbolAddress((void**)&pDinv, g_dinv);
    cudaGetSymbolAddress((void**)&pNorm, g_norm);
    cudaGetSymbolAddress((void**)&pStats, g_stats);
    cudaGetSymbolAddress((void**)&pDeg, g_deg);
    float* pS0 = pStats;
    float* pS1 = pStats + 128;
    float* pS2 = pStats + 256;

    const int TB = 256;
    const int gn = (n + TB - 1) / TB;
    const int ge = (e + TB - 1) / TB;
    const int STATS_BLOCKS = 1184;

    // degree / norm
    k_deg_init<<<gn, TB>>>(pDeg, n);
    k_deg_count<<<ge, TB>>>(dst, pDeg, e);
    k_dinv<<<gn, TB>>>(pDeg, pDinv, n);
    k_norm<<<ge, TB>>>(src, dst, pDinv, pNorm, e);

    // ---- layer 1: 4 -> 16, accum in C ----
    {
        constexpr int F = 16;
        k_gemm_init<4, F><<<gn, TB>>>(x, W1, b1, pDinv, pB, pC, pS0, n);
        int gs = (e * (F / 4) + TB - 1) / TB;
        k_scatter<F><<<gs, TB>>>(pB, src, dst, pNorm, pC, e);
        k_stats<F><<<STATS_BLOCKS, TB>>>(pC, pS0, n);
    }
    // ---- layer 2: 16 -> 32, reads C, accum in A ----
    {
        constexpr int F = 32;
        k_bn_gemm<16, F><<<gn, TB>>>(pC, pS0, g1, bt1, W2, b2, pDinv, pB, pA, pS1, n);
        int gs = (e * (F / 4) + TB - 1) / TB;
        k_scatter<F><<<gs, TB>>>(pB, src, dst, pNorm, pA, e);
        k_stats<F><<<STATS_BLOCKS, TB>>>(pA, pS1, n);
    }
    // ---- layer 3: 32 -> 64, reads A, accum in C ----
    {
        constexpr int F = 64;
        k_bn_gemm<32, F><<<gn, TB>>>(pA, pS1, g2, bt2, W3, b3, pDinv, pB, pC, pS2, n);
        int gs = (e * (F / 4) + TB - 1) / TB;
        k_scatter<F><<<gs, TB>>>(pB, src, dst, pNorm, pC, e);
        k_stats<F><<<STATS_BLOCKS, TB>>>(pC, pS2, n);
    }

    // ---- bn_elu of layer3 + MLP head + log_softmax ----
    k_mlp<<<(n + 127) / 128, 128>>>(pC, pS2, g3, bt3, Wf1, bf1, Wf2, bf2, Wf3, bf3, out, n);
}

// round 4
// speedup vs baseline: 1.1549x; 1.1549x over previous
#include <cuda_runtime.h>
#include <math.h>

#define N_NODES 100000
#define E_EDGES 1200000
#define EPS 1e-5f

// -------- scratch (device globals; no allocation allowed) --------
__device__ float g_A[N_NODES * 64];     // ping-pong conv output
__device__ float g_B[N_NODES * 64];     // h = (bn_elu(prev) or x) @ W
__device__ float g_C[N_NODES * 64];     // ping-pong conv output
__device__ float g_dinv[N_NODES];
__device__ int   g_deg[N_NODES];        // 1 + in-degree
__device__ int   g_rowptr[N_NODES + 1];
__device__ int   g_cursor[N_NODES];
__device__ int   g_srcs[E_EDGES];       // src ids sorted by dst
__device__ float g_norms[E_EDGES];      // per-edge norm, sorted by dst
__device__ int   g_partial[512];
__device__ int   g_blockOff[512];
__device__ float g_stats[3][128];       // per-layer: [0..63] sum, [64..127] sumsq

// ----------------- degree -----------------
__global__ void k_deg_init(int* deg, int n) {
    int i = blockIdx.x * blockDim.x + threadIdx.x;
    if (i < n) deg[i] = 1;  // self loop
}

__global__ void k_deg_count(const int* __restrict__ dst, int* deg, int e) {
    int i = blockIdx.x * blockDim.x + threadIdx.x;
    if (i < e) atomicAdd(&deg[dst[i]], 1);
}

__global__ void k_dinv(const int* __restrict__ deg, float* dinv, int n) {
    int i = blockIdx.x * blockDim.x + threadIdx.x;
    if (i < n) dinv[i] = rsqrtf((float)deg[i]);
}

// ----------------- CSR build: prefix sum over edge-degrees -----------------
__global__ void k_block_sums(const int* __restrict__ deg, int* partial, int n) {
    __shared__ int s[256];
    int i = blockIdx.x * 256 + threadIdx.x;
    s[threadIdx.x] = (i < n) ? (deg[i] - 1) : 0;
    __syncthreads();
    for (int off = 128; off > 0; off >>= 1) {
        if (threadIdx.x < off) s[threadIdx.x] += s[threadIdx.x + off];
        __syncthreads();
    }
    if (threadIdx.x == 0) partial[blockIdx.x] = s[0];
}

__global__ void k_scan_partials(const int* __restrict__ partial, int* blockOff, int nb) {
    __shared__ int s[512];
    int t = threadIdx.x;
    int mine = (t < nb) ? partial[t] : 0;
    s[t] = mine;
    __syncthreads();
    for (int off = 1; off < 512; off <<= 1) {
        int v = (t >= off) ? s[t - off] : 0;
        __syncthreads();
        s[t] += v;
        __syncthreads();
    }
    if (t < nb) blockOff[t] = s[t] - mine;  // exclusive
}

__global__ void k_rowptr(const int* __restrict__ deg, const int* __restrict__ blockOff,
                         int* rowptr, int* cursor, int n) {
    __shared__ int s[256];
    int t = threadIdx.x;
    int i = blockIdx.x * 256 + t;
    int v = (i < n) ? (deg[i] - 1) : 0;
    s[t] = v;
    __syncthreads();
    for (int off = 1; off < 256; off <<= 1) {
        int u = (t >= off) ? s[t - off] : 0;
        __syncthreads();
        s[t] += u;
        __syncthreads();
    }
    if (i < n) {
        int ex = blockOff[blockIdx.x] + s[t] - v;
        rowptr[i] = ex;
        cursor[i] = ex;
        if (i == n - 1) rowptr[n] = blockOff[blockIdx.x] + s[t];
    }
}

__global__ void k_place(const int* __restrict__ src, const int* __restrict__ dst,
                        const float* __restrict__ dinv, int* cursor,
                        int* src_sorted, float* norm_sorted, int e) {
    int i = blockIdx.x * blockDim.x + threadIdx.x;
    if (i >= e) return;
    int s = src[i], d = dst[i];
    int pos = atomicAdd(&cursor[d], 1);
    src_sorted[pos] = s;
    norm_sorted[pos] = __ldg(&dinv[s]) * __ldg(&dinv[d]);
}

// ----------------- layer-1 GEMM (h only) + zero stats -----------------
template <int FIN, int FOUT>
__global__ void k_gemm(const float* __restrict__ x, const float* __restrict__ W,
                       float* __restrict__ h, float* __restrict__ stats_zero, int n) {
    __shared__ float sW[FIN * FOUT];
    for (int i = threadIdx.x; i < FIN * FOUT; i += blockDim.x) sW[i] = W[i];
    if (blockIdx.x == 0 && threadIdx.x < 128) stats_zero[threadIdx.x] = 0.0f;
    __syncthreads();
    int node = blockIdx.x * blockDim.x + threadIdx.x;
    if (node >= n) return;
    float xv[FIN];
#pragma unroll
    for (int k = 0; k < FIN; k++) xv[k] = x[node * FIN + k];
#pragma unroll 4
    for (int j = 0; j < FOUT; j++) {
        float acc = 0.0f;
#pragma unroll
        for (int k = 0; k < FIN; k++) acc = fmaf(xv[k], sW[k * FOUT + j], acc);
        h[node * FOUT + j] = acc;
    }
}

// ----------------- fused relu+BN+ELU (prev layer) + GEMM (h only) + zero stats -----------------
template <int FIN, int FOUT>
__global__ void k_bn_gemm(const float* __restrict__ c, const float* __restrict__ stats_in,
                          const float* __restrict__ g, const float* __restrict__ bt,
                          const float* __restrict__ W,
                          float* __restrict__ h, float* __restrict__ stats_zero, int n) {
    __shared__ float sW[FIN * FOUT];
    __shared__ float smean[FIN], sscale[FIN], sbt[FIN];
    for (int i = threadIdx.x; i < FIN * FOUT; i += blockDim.x) sW[i] = W[i];
    if (threadIdx.x < FIN) {
        int col = threadIdx.x;
        float inv_n = 1.0f / (float)n;
        float mean = stats_in[col] * inv_n;
        float var = stats_in[64 + col] * inv_n - mean * mean;
        smean[col] = mean;
        sscale[col] = rsqrtf(var + EPS) * g[col];
        sbt[col] = bt[col];
    }
    if (blockIdx.x == 0 && threadIdx.x < 128) stats_zero[threadIdx.x] = 0.0f;
    __syncthreads();
    int node = blockIdx.x * blockDim.x + threadIdx.x;
    if (node >= n) return;
    float xv[FIN];
#pragma unroll
    for (int k = 0; k < FIN; k++) {
        float v = fmaxf(c[node * FIN + k], 0.0f);
        float y = (v - smean[k]) * sscale[k] + sbt[k];
        xv[k] = (y > 0.0f) ? y : expm1f(y);
    }
#pragma unroll 4
    for (int j = 0; j < FOUT; j++) {
        float acc = 0.0f;
#pragma unroll
        for (int k = 0; k < FIN; k++) acc = fmaf(xv[k], sW[k * FOUT + j], acc);
        h[node * FOUT + j] = acc;
    }
}

// ----------------- CSR gather conv + bias + fused relu-stats -----------------
// out[node] = b + dinv[node]^2 * h[node] + sum_{edges->node} norm_e * h[src_e]
// Group of G = F/4 threads per node; each thread owns a float4 column quad.
template <int F>
__global__ void __launch_bounds__(256)
k_gather_stats(const float* __restrict__ h, const int* __restrict__ rowptr,
               const int* __restrict__ src_sorted, const float* __restrict__ norm_sorted,
               const float* __restrict__ dinv, const float* __restrict__ b,
               float* __restrict__ outc, float* __restrict__ stats, int n) {
    constexpr int G = F / 4;
    __shared__ float sSum[F], sSq[F];
    __shared__ __align__(16) float sb[F];
    if (threadIdx.x < F) {
        sSum[threadIdx.x] = 0.0f;
        sSq[threadIdx.x] = 0.0f;
        sb[threadIdx.x] = b[threadIdx.x];
    }
    __syncthreads();

    int node = (blockIdx.x * blockDim.x + threadIdx.x) / G;
    int q = threadIdx.x & (G - 1);

    float4 acc = make_float4(0.f, 0.f, 0.f, 0.f);
    if (node < n) {
        const float4* h4 = reinterpret_cast<const float4*>(h);
        float di = dinv[node];
        float di2 = di * di;
        float4 bq = reinterpret_cast<const float4*>(sb)[q];
        float4 hv = h4[(size_t)node * G + q];
        acc.x = fmaf(di2, hv.x, bq.x);
        acc.y = fmaf(di2, hv.y, bq.y);
        acc.z = fmaf(di2, hv.z, bq.z);
        acc.w = fmaf(di2, hv.w, bq.w);
        int beg = rowptr[node], end = rowptr[node + 1];
        for (int i = beg; i < end; i++) {
            int s = __ldg(&src_sorted[i]);
            float nv = __ldg(&norm_sorted[i]);
            float4 sv = h4[(size_t)s * G + q];
            acc.x = fmaf(nv, sv.x, acc.x);
            acc.y = fmaf(nv, sv.y, acc.y);
            acc.z = fmaf(nv, sv.z, acc.z);
            acc.w = fmaf(nv, sv.w, acc.w);
        }
        reinterpret_cast<float4*>(outc)[(size_t)node * G + q] = acc;
    }

    // relu + sum/sumsq; warp-shuffle reduce across node-groups (period G in lane id)
    float r0 = fmaxf(acc.x, 0.f), r1 = fmaxf(acc.y, 0.f);
    float r2 = fmaxf(acc.z, 0.f), r3 = fmaxf(acc.w, 0.f);
    float q0 = r0 * r0, q1 = r1 * r1, q2 = r2 * r2, q3 = r3 * r3;
#pragma unroll
    for (int off = G; off < 32; off <<= 1) {
        r0 += __shfl_xor_sync(0xffffffffu, r0, off);
        r1 += __shfl_xor_sync(0xffffffffu, r1, off);
        r2 += __shfl_xor_sync(0xffffffffu, r2, off);
        r3 += __shfl_xor_sync(0xffffffffu, r3, off);
        q0 += __shfl_xor_sync(0xffffffffu, q0, off);
        q1 += __shfl_xor_sync(0xffffffffu, q1, off);
        q2 += __shfl_xor_sync(0xffffffffu, q2, off);
        q3 += __shfl_xor_sync(0xffffffffu, q3, off);
    }
    int lane = threadIdx.x & 31;
    if (lane < G) {
        int col = lane * 4;
        atomicAdd(&sSum[col + 0], r0);
        atomicAdd(&sSum[col + 1], r1);
        atomicAdd(&sSum[col + 2], r2);
        atomicAdd(&sSum[col + 3], r3);
        atomicAdd(&sSq[col + 0], q0);
        atomicAdd(&sSq[col + 1], q1);
        atomicAdd(&sSq[col + 2], q2);
        atomicAdd(&sSq[col + 3], q3);
    }
    __syncthreads();
    if (threadIdx.x < F) {
        atomicAdd(&stats[threadIdx.x], sSum[threadIdx.x]);
        atomicAdd(&stats[64 + threadIdx.x], sSq[threadIdx.x]);
    }
}

// ----------------- fused relu+BN+ELU + MLP + log_softmax -----------------
__global__ void __launch_bounds__(128)
k_mlp(const float* __restrict__ c, const float* __restrict__ stats_in,
      const float* __restrict__ g, const float* __restrict__ bt,
      const float* __restrict__ Wf1, const float* __restrict__ bf1,
      const float* __restrict__ Wf2, const float* __restrict__ bf2,
      const float* __restrict__ Wf3, const float* __restrict__ bf3,
      float* __restrict__ out, int n) {
    __shared__ float sW1[64 * 32], sb1[32];
    __shared__ float sW2[32 * 16], sb2[16];
    __shared__ float sW3[16 * 2], sb3[2];
    __shared__ float smean[64], sscale[64], sbt[64];
    for (int i = threadIdx.x; i < 64 * 32; i += blockDim.x) sW1[i] = Wf1[i];
    for (int i = threadIdx.x; i < 32 * 16; i += blockDim.x) sW2[i] = Wf2[i];
    for (int i = threadIdx.x; i < 32; i += blockDim.x) sW3[i] = Wf3[i];
    if (threadIdx.x < 32) sb1[threadIdx.x] = bf1[threadIdx.x];
    if (threadIdx.x < 16) sb2[threadIdx.x] = bf2[threadIdx.x];
    if (threadIdx.x < 2) sb3[threadIdx.x] = bf3[threadIdx.x];
    if (threadIdx.x < 64) {
        int col = threadIdx.x;
        float inv_n = 1.0f / (float)n;
        float mean = stats_in[col] * inv_n;
        float var = stats_in[64 + col] * inv_n - mean * mean;
        smean[col] = mean;
        sscale[col] = rsqrtf(var + EPS) * g[col];
        sbt[col] = bt[col];
    }
    __syncthreads();
    int node = blockIdx.x * blockDim.x + threadIdx.x;
    if (node >= n) return;

    float x[64];
    const float4* hp = reinterpret_cast<const float4*>(c + (size_t)node * 64);
#pragma unroll
    for (int k4 = 0; k4 < 16; k4++) {
        float4 v4 = hp[k4];
        float tmp[4] = {v4.x, v4.y, v4.z, v4.w};
#pragma unroll
        for (int j = 0; j < 4; j++) {
            int k = k4 * 4 + j;
            float v = fmaxf(tmp[j], 0.0f);
            float y = (v - smean[k]) * sscale[k] + sbt[k];
            x[k] = (y > 0.0f) ? y : expm1f(y);
        }
    }

    float t1[32];
#pragma unroll 4
    for (int j = 0; j < 32; j++) {
        float acc = sb1[j];
#pragma unroll
        for (int k = 0; k < 64; k++) acc = fmaf(x[k], sW1[k * 32 + j], acc);
        t1[j] = (acc > 0.0f) ? acc : expm1f(acc);
    }

    float t2[16];
#pragma unroll 4
    for (int j = 0; j < 16; j++) {
        float acc = sb2[j];
#pragma unroll
        for (int k = 0; k < 32; k++) acc = fmaf(t1[k], sW2[k * 16 + j], acc);
        t2[j] = (acc > 0.0f) ? acc : expm1f(acc);
    }

    float o0 = sb3[0], o1 = sb3[1];
#pragma unroll
    for (int k = 0; k < 16; k++) {
        o0 = fmaf(t2[k], sW3[k * 2 + 0], o0);
        o1 = fmaf(t2[k], sW3[k * 2 + 1], o1);
    }
    float m = fmaxf(o0, o1);
    float lse = m + logf(expf(o0 - m) + expf(o1 - m));
    out[node * 2 + 0] = o0 - lse;
    out[node * 2 + 1] = o1 - lse;
}

// ----------------- launch -----------------
extern "C" void kernel_launch(void* const* d_in, const int* in_sizes, int n_in,
                              void* d_out, int out_size) {
    const float* x   = (const float*)d_in[0];
    const int* eidx  = (const int*)d_in[1];
    const float* W1  = (const float*)d_in[2];
    const float* b1  = (const float*)d_in[3];
    const float* g1  = (const float*)d_in[4];
    const float* bt1 = (const float*)d_in[5];
    const float* W2  = (const float*)d_in[6];
    const float* b2  = (const float*)d_in[7];
    const float* g2  = (const float*)d_in[8];
    const float* bt2 = (const float*)d_in[9];
    const float* W3  = (const float*)d_in[10];
    const float* b3  = (const float*)d_in[11];
    const float* g3  = (const float*)d_in[12];
    const float* bt3 = (const float*)d_in[13];
    const float* Wf1 = (const float*)d_in[14];
    const float* bf1 = (const float*)d_in[15];
    const float* Wf2 = (const float*)d_in[16];
    const float* bf2 = (const float*)d_in[17];
    const float* Wf3 = (const float*)d_in[18];
    const float* bf3 = (const float*)d_in[19];
    float* out = (float*)d_out;

    const int n = in_sizes[0] / 4;
    const int e = in_sizes[1] / 2;
    const int* src = eidx;
    const int* dst = eidx + e;

    float *pA, *pB, *pC, *pDinv, *pNorms, *pStats;
    int *pDeg, *pRowptr, *pCursor, *pSrcs, *pPartial, *pBlockOff;
    cudaGetSymbolAddress((void**)&pA, g_A);
    cudaGetSymbolAddress((void**)&pB, g_B);
    cudaGetSymbolAddress((void**)&pC, g_C);
    cudaGetSymbolAddress((void**)&pDinv, g_dinv);
    cudaGetSymbolAddress((void**)&pDeg, g_deg);
    cudaGetSymbolAddress((void**)&pRowptr, g_rowptr);
    cudaGetSymbolAddress((void**)&pCursor, g_cursor);
    cudaGetSymbolAddress((void**)&pSrcs, g_srcs);
    cudaGetSymbolAddress((void**)&pNorms, g_norms);
    cudaGetSymbolAddress((void**)&pPartial, g_partial);
    cudaGetSymbolAddress((void**)&pBlockOff, g_blockOff);
    cudaGetSymbolAddress((void**)&pStats, g_stats);
    float* pS0 = pStats;
    float* pS1 = pStats + 128;
    float* pS2 = pStats + 256;

    const int TB = 256;
    const int gn = (n + TB - 1) / TB;   // 391 blocks
    const int ge = (e + TB - 1) / TB;

    // degree / dinv
    k_deg_init<<<gn, TB>>>(pDeg, n);
    k_deg_count<<<ge, TB>>>(dst, pDeg, e);
    k_dinv<<<gn, TB>>>(pDeg, pDinv, n);

    // CSR build
    k_block_sums<<<gn, TB>>>(pDeg, pPartial, n);
    k_scan_partials<<<1, 512>>>(pPartial, pBlockOff, gn);
    k_rowptr<<<gn, TB>>>(pDeg, pBlockOff, pRowptr, pCursor, n);
    k_place<<<ge, TB>>>(src, dst, pDinv, pCursor, pSrcs, pNorms, e);

    // ---- layer 1: 4 -> 16 ----
    {
        constexpr int F = 16;
        k_gemm<4, F><<<gn, TB>>>(x, W1, pB, pS0, n);
        int gg = (n * (F / 4) + TB - 1) / TB;
        k_gather_stats<F><<<gg, TB>>>(pB, pRowptr, pSrcs, pNorms, pDinv, b1, pC, pS0, n);
    }
    // ---- layer 2: 16 -> 32 ----
    {
        constexpr int F = 32;
        k_bn_gemm<16, F><<<gn, TB>>>(pC, pS0, g1, bt1, W2, pB, pS1, n);
        int gg = (n * (F / 4) + TB - 1) / TB;
        k_gather_stats<F><<<gg, TB>>>(pB, pRowptr, pSrcs, pNorms, pDinv, b2, pA, pS1, n);
    }
    // ---- layer 3: 32 -> 64 ----
    {
        constexpr int F = 64;
        k_bn_gemm<32, F><<<gn, TB>>>(pA, pS1, g2, bt2, W3, pB, pS2, n);
        int gg = (n * (F / 4) + TB - 1) / TB;
        k_gather_stats<F><<<gg, TB>>>(pB, pRowptr, pSrcs, pNorms, pDinv, b3, pC, pS2, n);
    }

    // ---- bn_elu of layer3 + MLP head + log_softmax ----
    k_mlp<<<(n + 127) / 128, 128>>>(pC, pS2, g3, bt3, Wf1, bf1, Wf2, bf2, Wf3, bf3, out, n);
}

// round 5
// speedup vs baseline: 1.1598x; 1.0042x over previous
#include <cuda_runtime.h>
#include <math.h>

#define N_NODES 100000
#define E_EDGES 1200000
#define EPS 1e-5f

// -------- scratch (device globals; no allocation allowed) --------
__device__ float g_A[N_NODES * 64];     // ping-pong conv output
__device__ float g_B[N_NODES * 64];     // h = (bn_elu(prev) or x) @ W
__device__ float g_C[N_NODES * 64];     // ping-pong conv output
__device__ float g_dinv[N_NODES];
__device__ int   g_deg[N_NODES];        // 1 + in-degree
__device__ int   g_rowptr[N_NODES + 1];
__device__ int   g_cursor[N_NODES];
__device__ int2  g_edge[E_EDGES];       // {src, bits(norm)} sorted by dst
__device__ int   g_partial[512];
__device__ int   g_blockOff[512];
__device__ float g_stats[3][128];       // per-layer: [0..63] sum, [64..127] sumsq

// ----------------- degree -----------------
__global__ void k_deg_init(int* deg, int n) {
    int i = blockIdx.x * blockDim.x + threadIdx.x;
    if (i < n) deg[i] = 1;  // self loop
}

__global__ void k_deg_count(const int* __restrict__ dst, int* deg, int e) {
    int i = blockIdx.x * blockDim.x + threadIdx.x;
    if (i < e) atomicAdd(&deg[dst[i]], 1);
}

__global__ void k_dinv(const int* __restrict__ deg, float* dinv, int n) {
    int i = blockIdx.x * blockDim.x + threadIdx.x;
    if (i < n) dinv[i] = rsqrtf((float)deg[i]);
}

// ----------------- CSR build: prefix sum over edge-degrees -----------------
__global__ void k_block_sums(const int* __restrict__ deg, int* partial, int n) {
    __shared__ int s[256];
    int i = blockIdx.x * 256 + threadIdx.x;
    s[threadIdx.x] = (i < n) ? (deg[i] - 1) : 0;
    __syncthreads();
    for (int off = 128; off > 0; off >>= 1) {
        if (threadIdx.x < off) s[threadIdx.x] += s[threadIdx.x + off];
        __syncthreads();
    }
    if (threadIdx.x == 0) partial[blockIdx.x] = s[0];
}

__global__ void k_scan_partials(const int* __restrict__ partial, int* blockOff, int nb) {
    __shared__ int s[512];
    int t = threadIdx.x;
    int mine = (t < nb) ? partial[t] : 0;
    s[t] = mine;
    __syncthreads();
    for (int off = 1; off < 512; off <<= 1) {
        int v = (t >= off) ? s[t - off] : 0;
        __syncthreads();
        s[t] += v;
        __syncthreads();
    }
    if (t < nb) blockOff[t] = s[t] - mine;  // exclusive
}

__global__ void k_rowptr(const int* __restrict__ deg, const int* __restrict__ blockOff,
                         int* rowptr, int* cursor, int n) {
    __shared__ int s[256];
    int t = threadIdx.x;
    int i = blockIdx.x * 256 + t;
    int v = (i < n) ? (deg[i] - 1) : 0;
    s[t] = v;
    __syncthreads();
    for (int off = 1; off < 256; off <<= 1) {
        int u = (t >= off) ? s[t - off] : 0;
        __syncthreads();
        s[t] += u;
        __syncthreads();
    }
    if (i < n) {
        int ex = blockOff[blockIdx.x] + s[t] - v;
        rowptr[i] = ex;
        cursor[i] = ex;
        if (i == n - 1) rowptr[n] = blockOff[blockIdx.x] + s[t];
    }
}

__global__ void k_place(const int* __restrict__ src, const int* __restrict__ dst,
                        const float* __restrict__ dinv, int* cursor,
                        int2* edge_sorted, int e) {
    int i = blockIdx.x * blockDim.x + threadIdx.x;
    if (i >= e) return;
    int s = src[i], d = dst[i];
    int pos = atomicAdd(&cursor[d], 1);
    float nv = __ldg(&dinv[s]) * __ldg(&dinv[d]);
    edge_sorted[pos] = make_int2(s, __float_as_int(nv));
}

// ----------------- layer-1 GEMM (h only) + zero stats -----------------
template <int FIN, int FOUT>
__global__ void k_gemm(const float* __restrict__ x, const float* __restrict__ W,
                       float* __restrict__ h, float* __restrict__ stats_zero, int n) {
    __shared__ float sW[FIN * FOUT];
    for (int i = threadIdx.x; i < FIN * FOUT; i += blockDim.x) sW[i] = W[i];
    if (blockIdx.x == 0 && threadIdx.x < 128) stats_zero[threadIdx.x] = 0.0f;
    __syncthreads();
    int node = blockIdx.x * blockDim.x + threadIdx.x;
    if (node >= n) return;
    float xv[FIN];
#pragma unroll
    for (int k = 0; k < FIN; k++) xv[k] = x[node * FIN + k];
#pragma unroll 4
    for (int j = 0; j < FOUT; j++) {
        float acc = 0.0f;
#pragma unroll
        for (int k = 0; k < FIN; k++) acc = fmaf(xv[k], sW[k * FOUT + j], acc);
        h[node * FOUT + j] = acc;
    }
}

// ----------------- fused relu+BN+ELU (prev layer) + GEMM (h only) + zero stats -----------------
template <int FIN, int FOUT>
__global__ void k_bn_gemm(const float* __restrict__ c, const float* __restrict__ stats_in,
                          const float* __restrict__ g, const float* __restrict__ bt,
                          const float* __restrict__ W,
                          float* __restrict__ h, float* __restrict__ stats_zero, int n) {
    __shared__ float sW[FIN * FOUT];
    __shared__ float smean[FIN], sscale[FIN], sbt[FIN];
    for (int i = threadIdx.x; i < FIN * FOUT; i += blockDim.x) sW[i] = W[i];
    if (threadIdx.x < FIN) {
        int col = threadIdx.x;
        float inv_n = 1.0f / (float)n;
        float mean = stats_in[col] * inv_n;
        float var = stats_in[64 + col] * inv_n - mean * mean;
        smean[col] = mean;
        sscale[col] = rsqrtf(var + EPS) * g[col];
        sbt[col] = bt[col];
    }
    if (blockIdx.x == 0 && threadIdx.x < 128) stats_zero[threadIdx.x] = 0.0f;
    __syncthreads();
    int node = blockIdx.x * blockDim.x + threadIdx.x;
    if (node >= n) return;
    float xv[FIN];
#pragma unroll
    for (int k = 0; k < FIN; k++) {
        float v = fmaxf(c[node * FIN + k], 0.0f);
        float y = (v - smean[k]) * sscale[k] + sbt[k];
        xv[k] = (y > 0.0f) ? y : expm1f(y);
    }
#pragma unroll 4
    for (int j = 0; j < FOUT; j++) {
        float acc = 0.0f;
#pragma unroll
        for (int k = 0; k < FIN; k++) acc = fmaf(xv[k], sW[k * FOUT + j], acc);
        h[node * FOUT + j] = acc;
    }
}

// ----------------- CSR gather conv + bias + fused relu-stats -----------------
// out[node] = b + dinv[node]^2 * h[node] + sum_{edges->node} norm_e * h[src_e]
// Group of G = F/4 threads per node; edge loop unrolled x4 with independent
// accumulators to raise MLP on the index->data dependent-load chain.
template <int F>
__global__ void __launch_bounds__(256)
k_gather_stats(const float* __restrict__ h, const int* __restrict__ rowptr,
               const int2* __restrict__ edges,
               const float* __restrict__ dinv, const float* __restrict__ b,
               float* __restrict__ outc, float* __restrict__ stats, int n) {
    constexpr int G = F / 4;
    __shared__ float sSum[F], sSq[F];
    __shared__ __align__(16) float sb[F];
    if (threadIdx.x < F) {
        sSum[threadIdx.x] = 0.0f;
        sSq[threadIdx.x] = 0.0f;
        sb[threadIdx.x] = b[threadIdx.x];
    }
    __syncthreads();

    int node = (blockIdx.x * blockDim.x + threadIdx.x) / G;
    int q = threadIdx.x & (G - 1);

    float4 acc = make_float4(0.f, 0.f, 0.f, 0.f);
    if (node < n) {
        const float4* h4 = reinterpret_cast<const float4*>(h);
        float di = dinv[node];
        float di2 = di * di;
        float4 bq = reinterpret_cast<const float4*>(sb)[q];
        float4 hv = h4[(size_t)node * G + q];
        float4 a0, a1, a2, a3;
        a0.x = fmaf(di2, hv.x, bq.x);
        a0.y = fmaf(di2, hv.y, bq.y);
        a0.z = fmaf(di2, hv.z, bq.z);
        a0.w = fmaf(di2, hv.w, bq.w);
        a1 = make_float4(0.f, 0.f, 0.f, 0.f);
        a2 = make_float4(0.f, 0.f, 0.f, 0.f);
        a3 = make_float4(0.f, 0.f, 0.f, 0.f);

        int beg = rowptr[node], end = rowptr[node + 1];
        int i = beg;
        for (; i + 4 <= end; i += 4) {
            int2 e0 = __ldg(&edges[i + 0]);
            int2 e1 = __ldg(&edges[i + 1]);
            int2 e2 = __ldg(&edges[i + 2]);
            int2 e3 = __ldg(&edges[i + 3]);
            float4 s0 = h4[(size_t)e0.x * G + q];
            float4 s1 = h4[(size_t)e1.x * G + q];
            float4 s2 = h4[(size_t)e2.x * G + q];
            float4 s3 = h4[(size_t)e3.x * G + q];
            float n0 = __int_as_float(e0.y);
            float n1 = __int_as_float(e1.y);
            float n2 = __int_as_float(e2.y);
            float n3 = __int_as_float(e3.y);
            a0.x = fmaf(n0, s0.x, a0.x); a0.y = fmaf(n0, s0.y, a0.y);
            a0.z = fmaf(n0, s0.z, a0.z); a0.w = fmaf(n0, s0.w, a0.w);
            a1.x = fmaf(n1, s1.x, a1.x); a1.y = fmaf(n1, s1.y, a1.y);
            a1.z = fmaf(n1, s1.z, a1.z); a1.w = fmaf(n1, s1.w, a1.w);
            a2.x = fmaf(n2, s2.x, a2.x); a2.y = fmaf(n2, s2.y, a2.y);
            a2.z = fmaf(n2, s2.z, a2.z); a2.w = fmaf(n2, s2.w, a2.w);
            a3.x = fmaf(n3, s3.x, a3.x); a3.y = fmaf(n3, s3.y, a3.y);
            a3.z = fmaf(n3, s3.z, a3.z); a3.w = fmaf(n3, s3.w, a3.w);
        }
        for (; i < end; i++) {
            int2 e0 = __ldg(&edges[i]);
            float4 s0 = h4[(size_t)e0.x * G + q];
            float n0 = __int_as_float(e0.y);
            a1.x = fmaf(n0, s0.x, a1.x); a1.y = fmaf(n0, s0.y, a1.y);
            a1.z = fmaf(n0, s0.z, a1.z); a1.w = fmaf(n0, s0.w, a1.w);
        }
        acc.x = (a0.x + a1.x) + (a2.x + a3.x);
        acc.y = (a0.y + a1.y) + (a2.y + a3.y);
        acc.z = (a0.z + a1.z) + (a2.z + a3.z);
        acc.w = (a0.w + a1.w) + (a2.w + a3.w);
        reinterpret_cast<float4*>(outc)[(size_t)node * G + q] = acc;
    }

    // relu + sum/sumsq; warp-shuffle reduce across node-groups (period G in lane id)
    float r0 = fmaxf(acc.x, 0.f), r1 = fmaxf(acc.y, 0.f);
    float r2 = fmaxf(acc.z, 0.f), r3 = fmaxf(acc.w, 0.f);
    float q0 = r0 * r0, q1 = r1 * r1, q2 = r2 * r2, q3 = r3 * r3;
#pragma unroll
    for (int off = G; off < 32; off <<= 1) {
        r0 += __shfl_xor_sync(0xffffffffu, r0, off);
        r1 += __shfl_xor_sync(0xffffffffu, r1, off);
        r2 += __shfl_xor_sync(0xffffffffu, r2, off);
        r3 += __shfl_xor_sync(0xffffffffu, r3, off);
        q0 += __shfl_xor_sync(0xffffffffu, q0, off);
        q1 += __shfl_xor_sync(0xffffffffu, q1, off);
        q2 += __shfl_xor_sync(0xffffffffu, q2, off);
        q3 += __shfl_xor_sync(0xffffffffu, q3, off);
    }
    int lane = threadIdx.x & 31;
    if (lane < G) {
        int col = lane * 4;
        atomicAdd(&sSum[col + 0], r0);
        atomicAdd(&sSum[col + 1], r1);
        atomicAdd(&sSum[col + 2], r2);
        atomicAdd(&sSum[col + 3], r3);
        atomicAdd(&sSq[col + 0], q0);
        atomicAdd(&sSq[col + 1], q1);
        atomicAdd(&sSq[col + 2], q2);
        atomicAdd(&sSq[col + 3], q3);
    }
    __syncthreads();
    if (threadIdx.x < F) {
        atomicAdd(&stats[threadIdx.x], sSum[threadIdx.x]);
        atomicAdd(&stats[64 + threadIdx.x], sSq[threadIdx.x]);
    }
}

// ----------------- fused relu+BN+ELU + MLP + log_softmax -----------------
__global__ void __launch_bounds__(128)
k_mlp(const float* __restrict__ c, const float* __restrict__ stats_in,
      const float* __restrict__ g, const float* __restrict__ bt,
      const float* __restrict__ Wf1, const float* __restrict__ bf1,
      const float* __restrict__ Wf2, const float* __restrict__ bf2,
      const float* __restrict__ Wf3, const float* __restrict__ bf3,
      float* __restrict__ out, int n) {
    __shared__ float sW1[64 * 32], sb1[32];
    __shared__ float sW2[32 * 16], sb2[16];
    __shared__ float sW3[16 * 2], sb3[2];
    __shared__ float smean[64], sscale[64], sbt[64];
    for (int i = threadIdx.x; i < 64 * 32; i += blockDim.x) sW1[i] = Wf1[i];
    for (int i = threadIdx.x; i < 32 * 16; i += blockDim.x) sW2[i] = Wf2[i];
    for (int i = threadIdx.x; i < 32; i += blockDim.x) sW3[i] = Wf3[i];
    if (threadIdx.x < 32) sb1[threadIdx.x] = bf1[threadIdx.x];
    if (threadIdx.x < 16) sb2[threadIdx.x] = bf2[threadIdx.x];
    if (threadIdx.x < 2) sb3[threadIdx.x] = bf3[threadIdx.x];
    if (threadIdx.x < 64) {
        int col = threadIdx.x;
        float inv_n = 1.0f / (float)n;
        float mean = stats_in[col] * inv_n;
        float var = stats_in[64 + col] * inv_n - mean * mean;
        smean[col] = mean;
        sscale[col] = rsqrtf(var + EPS) * g[col];
        sbt[col] = bt[col];
    }
    __syncthreads();
    int node = blockIdx.x * blockDim.x + threadIdx.x;
    if (node >= n) return;

    float x[64];
    const float4* hp = reinterpret_cast<const float4*>(c + (size_t)node * 64);
#pragma unroll
    for (int k4 = 0; k4 < 16; k4++) {
        float4 v4 = hp[k4];
        float tmp[4] = {v4.x, v4.y, v4.z, v4.w};
#pragma unroll
        for (int j = 0; j < 4; j++) {
            int k = k4 * 4 + j;
            float v = fmaxf(tmp[j], 0.0f);
            float y = (v - smean[k]) * sscale[k] + sbt[k];
            x[k] = (y > 0.0f) ? y : expm1f(y);
        }
    }

    float t1[32];
#pragma unroll 4
    for (int j = 0; j < 32; j++) {
        float acc = sb1[j];
#pragma unroll
        for (int k = 0; k < 64; k++) acc = fmaf(x[k], sW1[k * 32 + j], acc);
        t1[j] = (acc > 0.0f) ? acc : expm1f(acc);
    }

    float t2[16];
#pragma unroll 4
    for (int j = 0; j < 16; j++) {
        float acc = sb2[j];
#pragma unroll
        for (int k = 0; k < 32; k++) acc = fmaf(t1[k], sW2[k * 16 + j], acc);
        t2[j] = (acc > 0.0f) ? acc : expm1f(acc);
    }

    float o0 = sb3[0], o1 = sb3[1];
#pragma unroll
    for (int k = 0; k < 16; k++) {
        o0 = fmaf(t2[k], sW3[k * 2 + 0], o0);
        o1 = fmaf(t2[k], sW3[k * 2 + 1], o1);
    }
    float m = fmaxf(o0, o1);
    float lse = m + logf(expf(o0 - m) + expf(o1 - m));
    out[node * 2 + 0] = o0 - lse;
    out[node * 2 + 1] = o1 - lse;
}

// ----------------- launch -----------------
extern "C" void kernel_launch(void* const* d_in, const int* in_sizes, int n_in,
                              void* d_out, int out_size) {
    const float* x   = (const float*)d_in[0];
    const int* eidx  = (const int*)d_in[1];
    const float* W1  = (const float*)d_in[2];
    const float* b1  = (const float*)d_in[3];
    const float* g1  = (const float*)d_in[4];
    const float* bt1 = (const float*)d_in[5];
    const float* W2  = (const float*)d_in[6];
    const float* b2  = (const float*)d_in[7];
    const float* g2  = (const float*)d_in[8];
    const float* bt2 = (const float*)d_in[9];
    const float* W3  = (const float*)d_in[10];
    const float* b3  = (const float*)d_in[11];
    const float* g3  = (const float*)d_in[12];
    const float* bt3 = (const float*)d_in[13];
    const float* Wf1 = (const float*)d_in[14];
    const float* bf1 = (const float*)d_in[15];
    const float* Wf2 = (const float*)d_in[16];
    const float* bf2 = (const float*)d_in[17];
    const float* Wf3 = (const float*)d_in[18];
    const float* bf3 = (const float*)d_in[19];
    float* out = (float*)d_out;

    const int n = in_sizes[0] / 4;
    const int e = in_sizes[1] / 2;
    const int* src = eidx;
    const int* dst = eidx + e;

    float *pA, *pB, *pC, *pDinv, *pStats;
    int *pDeg, *pRowptr, *pCursor, *pPartial, *pBlockOff;
    int2* pEdge;
    cudaGetSymbolAddress((void**)&pA, g_A);
    cudaGetSymbolAddress((void**)&pB, g_B);
    cudaGetSymbolAddress((void**)&pC, g_C);
    cudaGetSymbolAddress((void**)&pDinv, g_dinv);
    cudaGetSymbolAddress((void**)&pDeg, g_deg);
    cudaGetSymbolAddress((void**)&pRowptr, g_rowptr);
    cudaGetSymbolAddress((void**)&pCursor, g_cursor);
    cudaGetSymbolAddress((void**)&pEdge, g_edge);
    cudaGetSymbolAddress((void**)&pPartial, g_partial);
    cudaGetSymbolAddress((void**)&pBlockOff, g_blockOff);
    cudaGetSymbolAddress((void**)&pStats, g_stats);
    float* pS0 = pStats;
    float* pS1 = pStats + 128;
    float* pS2 = pStats + 256;

    const int TB = 256;
    const int gn = (n + TB - 1) / TB;   // 391 blocks
    const int ge = (e + TB - 1) / TB;

    // degree / dinv
    k_deg_init<<<gn, TB>>>(pDeg, n);
    k_deg_count<<<ge, TB>>>(dst, pDeg, e);
    k_dinv<<<gn, TB>>>(pDeg, pDinv, n);

    // CSR build
    k_block_sums<<<gn, TB>>>(pDeg, pPartial, n);
    k_scan_partials<<<1, 512>>>(pPartial, pBlockOff, gn);
    k_rowptr<<<gn, TB>>>(pDeg, pBlockOff, pRowptr, pCursor, n);
    k_place<<<ge, TB>>>(src, dst, pDinv, pCursor, pEdge, e);

    // ---- layer 1: 4 -> 16 ----
    {
        constexpr int F = 16;
        k_gemm<4, F><<<gn, TB>>>(x, W1, pB, pS0, n);
        int gg = (n * (F / 4) + TB - 1) / TB;
        k_gather_stats<F><<<gg, TB>>>(pB, pRowptr, pEdge, pDinv, b1, pC, pS0, n);
    }
    // ---- layer 2: 16 -> 32 ----
    {
        constexpr int F = 32;
        k_bn_gemm<16, F><<<gn, TB>>>(pC, pS0, g1, bt1, W2, pB, pS1, n);
        int gg = (n * (F / 4) + TB - 1) / TB;
        k_gather_stats<F><<<gg, TB>>>(pB, pRowptr, pEdge, pDinv, b2, pA, pS1, n);
    }
    // ---- layer 3: 32 -> 64 ----
    {
        constexpr int F = 64;
        k_bn_gemm<32, F><<<gn, TB>>>(pA, pS1, g2, bt2, W3, pB, pS2, n);
        int gg = (n * (F / 4) + TB - 1) / TB;
        k_gather_stats<F><<<gg, TB>>>(pB, pRowptr, pEdge, pDinv, b3, pC, pS2, n);
    }

    // ---- bn_elu of layer3 + MLP head + log_softmax ----
    k_mlp<<<(n + 127) / 128, 128>>>(pC, pS2, g3, bt3, Wf1, bf1, Wf2, bf2, Wf3, bf3, out, n);
}

// round 6
// speedup vs baseline: 1.1678x; 1.0069x over previous
#include <cuda_runtime.h>
#include <math.h>

#define N_NODES 100000
#define E_EDGES 1200000
#define EPS 1e-5f

// -------- scratch (device globals; no allocation allowed) --------
__device__ float g_A[N_NODES * 64];     // act (post bn+elu)
__device__ float g_B[N_NODES * 64];     // agg (aggregated features, pre-GEMM)
__device__ float g_C[N_NODES * 64];     // conv output (pre-BN)
__device__ float g_dinv[N_NODES];
__device__ int   g_deg[N_NODES];        // 1 + in-degree
__device__ int   g_rowptr[N_NODES + 1];
__device__ int   g_cursor[N_NODES];
__device__ int2  g_edge[E_EDGES];       // {src, bits(norm)} sorted by dst
__device__ int   g_partial[512];
__device__ int   g_blockOff[512];
__device__ float g_stats[3][128];       // per-layer: [0..63] sum, [64..127] sumsq

// ----------------- degree -----------------
__global__ void k_deg_init(int* deg, int n) {
    int i = blockIdx.x * blockDim.x + threadIdx.x;
    if (i < n) deg[i] = 1;  // self loop
}

__global__ void k_deg_count(const int* __restrict__ dst, int* deg, int e) {
    int i = blockIdx.x * blockDim.x + threadIdx.x;
    if (i < e) atomicAdd(&deg[dst[i]], 1);
}

// dinv + per-block partial sums of edge-degree (fused)
__global__ void k_dinv_blocksums(const int* __restrict__ deg, float* dinv,
                                 int* partial, int n) {
    __shared__ int s[256];
    int i = blockIdx.x * 256 + threadIdx.x;
    int d = (i < n) ? deg[i] : 1;
    if (i < n) dinv[i] = rsqrtf((float)d);
    s[threadIdx.x] = (i < n) ? (d - 1) : 0;
    __syncthreads();
    for (int off = 128; off > 0; off >>= 1) {
        if (threadIdx.x < off) s[threadIdx.x] += s[threadIdx.x + off];
        __syncthreads();
    }
    if (threadIdx.x == 0) partial[blockIdx.x] = s[0];
}

__global__ void k_scan_partials(const int* __restrict__ partial, int* blockOff, int nb) {
    __shared__ int s[512];
    int t = threadIdx.x;
    int mine = (t < nb) ? partial[t] : 0;
    s[t] = mine;
    __syncthreads();
    for (int off = 1; off < 512; off <<= 1) {
        int v = (t >= off) ? s[t - off] : 0;
        __syncthreads();
        s[t] += v;
        __syncthreads();
    }
    if (t < nb) blockOff[t] = s[t] - mine;  // exclusive
}

__global__ void k_rowptr(const int* __restrict__ deg, const int* __restrict__ blockOff,
                         int* rowptr, int* cursor, int n) {
    __shared__ int s[256];
    int t = threadIdx.x;
    int i = blockIdx.x * 256 + t;
    int v = (i < n) ? (deg[i] - 1) : 0;
    s[t] = v;
    __syncthreads();
    for (int off = 1; off < 256; off <<= 1) {
        int u = (t >= off) ? s[t - off] : 0;
        __syncthreads();
        s[t] += u;
        __syncthreads();
    }
    if (i < n) {
        int ex = blockOff[blockIdx.x] + s[t] - v;
        rowptr[i] = ex;
        cursor[i] = ex;
        if (i == n - 1) rowptr[n] = blockOff[blockIdx.x] + s[t];
    }
}

__global__ void k_place(const int* __restrict__ src, const int* __restrict__ dst,
                        const float* __restrict__ dinv, int* cursor,
                        int2* edge_sorted, int e) {
    int i = blockIdx.x * blockDim.x + threadIdx.x;
    if (i >= e) return;
    int s = src[i], d = dst[i];
    int pos = atomicAdd(&cursor[d], 1);
    float nv = __ldg(&dinv[s]) * __ldg(&dinv[d]);
    edge_sorted[pos] = make_int2(s, __float_as_int(nv));
}

// ----------------- CSR gather on INPUT features (F = FIN) -----------------
// agg[node] = dinv^2 * act[node] + sum_{edges->node} norm_e * act[src_e]
// Also zeroes this layer's stats slice (used later by the GEMM epilogue).
template <int F>
__global__ void __launch_bounds__(256)
k_gather(const float* __restrict__ act, const int* __restrict__ rowptr,
         const int2* __restrict__ edges, const float* __restrict__ dinv,
         float* __restrict__ agg, float* __restrict__ stats_zero, int n) {
    constexpr int G = F / 4;
    if (blockIdx.x == 0 && threadIdx.x < 128) stats_zero[threadIdx.x] = 0.0f;
    int gid = blockIdx.x * blockDim.x + threadIdx.x;
    int node = gid / G;
    int q = gid & (G - 1);
    if (node >= n) return;

    const float4* a4 = reinterpret_cast<const float4*>(act);
    float di = dinv[node];
    float di2 = di * di;
    float4 hv = a4[(size_t)node * G + q];
    float4 a0, a1, a2, a3;
    a0.x = di2 * hv.x; a0.y = di2 * hv.y; a0.z = di2 * hv.z; a0.w = di2 * hv.w;
    a1 = make_float4(0.f, 0.f, 0.f, 0.f);
    a2 = make_float4(0.f, 0.f, 0.f, 0.f);
    a3 = make_float4(0.f, 0.f, 0.f, 0.f);

    int beg = rowptr[node], end = rowptr[node + 1];
    int i = beg;
    for (; i + 4 <= end; i += 4) {
        int2 e0 = __ldg(&edges[i + 0]);
        int2 e1 = __ldg(&edges[i + 1]);
        int2 e2 = __ldg(&edges[i + 2]);
        int2 e3 = __ldg(&edges[i + 3]);
        float4 s0 = a4[(size_t)e0.x * G + q];
        float4 s1 = a4[(size_t)e1.x * G + q];
        float4 s2 = a4[(size_t)e2.x * G + q];
        float4 s3 = a4[(size_t)e3.x * G + q];
        float n0 = __int_as_float(e0.y);
        float n1 = __int_as_float(e1.y);
        float n2 = __int_as_float(e2.y);
        float n3 = __int_as_float(e3.y);
        a0.x = fmaf(n0, s0.x, a0.x); a0.y = fmaf(n0, s0.y, a0.y);
        a0.z = fmaf(n0, s0.z, a0.z); a0.w = fmaf(n0, s0.w, a0.w);
        a1.x = fmaf(n1, s1.x, a1.x); a1.y = fmaf(n1, s1.y, a1.y);
        a1.z = fmaf(n1, s1.z, a1.z); a1.w = fmaf(n1, s1.w, a1.w);
        a2.x = fmaf(n2, s2.x, a2.x); a2.y = fmaf(n2, s2.y, a2.y);
        a2.z = fmaf(n2, s2.z, a2.z); a2.w = fmaf(n2, s2.w, a2.w);
        a3.x = fmaf(n3, s3.x, a3.x); a3.y = fmaf(n3, s3.y, a3.y);
        a3.z = fmaf(n3, s3.z, a3.z); a3.w = fmaf(n3, s3.w, a3.w);
    }
    for (; i < end; i++) {
        int2 e0 = __ldg(&edges[i]);
        float4 s0 = a4[(size_t)e0.x * G + q];
        float n0 = __int_as_float(e0.y);
        a1.x = fmaf(n0, s0.x, a1.x); a1.y = fmaf(n0, s0.y, a1.y);
        a1.z = fmaf(n0, s0.z, a1.z); a1.w = fmaf(n0, s0.w, a1.w);
    }
    float4 acc;
    acc.x = (a0.x + a1.x) + (a2.x + a3.x);
    acc.y = (a0.y + a1.y) + (a2.y + a3.y);
    acc.z = (a0.z + a1.z) + (a2.z + a3.z);
    acc.w = (a0.w + a1.w) + (a2.w + a3.w);
    reinterpret_cast<float4*>(agg)[(size_t)node * G + q] = acc;
}

// ----------------- GEMM (agg @ W + b) + fused relu-stats epilogue -----------------
// NOTE: n % 32 == 0 in this problem (100000), so warps are fully active or fully idle.
template <int FIN, int FOUT>
__global__ void __launch_bounds__(256)
k_gemm_stats(const float* __restrict__ agg, const float* __restrict__ W,
             const float* __restrict__ b,
             float* __restrict__ outc, float* __restrict__ stats, int n) {
    __shared__ float sW[FIN * FOUT];
    __shared__ float sb[FOUT];
    __shared__ float sSum[FOUT], sSq[FOUT];
    for (int i = threadIdx.x; i < FIN * FOUT; i += blockDim.x) sW[i] = W[i];
    if (threadIdx.x < FOUT) {
        sb[threadIdx.x] = b[threadIdx.x];
        sSum[threadIdx.x] = 0.0f;
        sSq[threadIdx.x] = 0.0f;
    }
    __syncthreads();

    int node = blockIdx.x * blockDim.x + threadIdx.x;
    bool active = (node < n);
    int lane = threadIdx.x & 31;

    float xv[FIN];
#pragma unroll
    for (int k = 0; k < FIN; k++) xv[k] = active ? agg[(size_t)node * FIN + k] : 0.0f;

#pragma unroll 4
    for (int j = 0; j < FOUT; j++) {
        float acc = sb[j];
#pragma unroll
        for (int k = 0; k < FIN; k++) acc = fmaf(xv[k], sW[k * FOUT + j], acc);
        float r = active ? fmaxf(acc, 0.0f) : 0.0f;
        if (active) outc[(size_t)node * FOUT + j] = acc;
        float q = r * r;
#pragma unroll
        for (int off = 16; off > 0; off >>= 1) {
            r += __shfl_xor_sync(0xffffffffu, r, off);
            q += __shfl_xor_sync(0xffffffffu, q, off);
        }
        if (lane == 0) {
            atomicAdd(&sSum[j], r);
            atomicAdd(&sSq[j], q);
        }
    }
    __syncthreads();
    if (threadIdx.x < FOUT) {
        atomicAdd(&stats[threadIdx.x], sSum[threadIdx.x]);
        atomicAdd(&stats[64 + threadIdx.x], sSq[threadIdx.x]);
    }
}

// ----------------- relu + BN + ELU (elementwise) -----------------
template <int F>
__global__ void k_bn_elu(const float* __restrict__ c, const float* __restrict__ stats_in,
                         const float* __restrict__ g, const float* __restrict__ bt,
                         float* __restrict__ act, int n) {
    __shared__ float smean[F], sscale[F], sbt[F];
    if (threadIdx.x < F) {
        int col = threadIdx.x;
        float inv_n = 1.0f / (float)n;
        float mean = stats_in[col] * inv_n;
        float var = stats_in[64 + col] * inv_n - mean * mean;
        smean[col] = mean;
        sscale[col] = rsqrtf(var + EPS) * g[col];
        sbt[col] = bt[col];
    }
    __syncthreads();
    long idx = (long)blockIdx.x * blockDim.x + threadIdx.x;
    if (idx >= (long)n * F) return;
    int col = (int)(idx & (F - 1));
    float v = fmaxf(c[idx], 0.0f);
    float y = (v - smean[col]) * sscale[col] + sbt[col];
    act[idx] = (y > 0.0f) ? y : expm1f(y);
}

// ----------------- fused relu+BN+ELU + MLP + log_softmax -----------------
__global__ void __launch_bounds__(128)
k_mlp(const float* __restrict__ c, const float* __restrict__ stats_in,
      const float* __restrict__ g, const float* __restrict__ bt,
      const float* __restrict__ Wf1, const float* __restrict__ bf1,
      const float* __restrict__ Wf2, const float* __restrict__ bf2,
      const float* __restrict__ Wf3, const float* __restrict__ bf3,
      float* __restrict__ out, int n) {
    __shared__ float sW1[64 * 32], sb1[32];
    __shared__ float sW2[32 * 16], sb2[16];
    __shared__ float sW3[16 * 2], sb3[2];
    __shared__ float smean[64], sscale[64], sbt[64];
    for (int i = threadIdx.x; i < 64 * 32; i += blockDim.x) sW1[i] = Wf1[i];
    for (int i = threadIdx.x; i < 32 * 16; i += blockDim.x) sW2[i] = Wf2[i];
    for (int i = threadIdx.x; i < 32; i += blockDim.x) sW3[i] = Wf3[i];
    if (threadIdx.x < 32) sb1[threadIdx.x] = bf1[threadIdx.x];
    if (threadIdx.x < 16) sb2[threadIdx.x] = bf2[threadIdx.x];
    if (threadIdx.x < 2) sb3[threadIdx.x] = bf3[threadIdx.x];
    if (threadIdx.x < 64) {
        int col = threadIdx.x;
        float inv_n = 1.0f / (float)n;
        float mean = stats_in[col] * inv_n;
        float var = stats_in[64 + col] * inv_n - mean * mean;
        smean[col] = mean;
        sscale[col] = rsqrtf(var + EPS) * g[col];
        sbt[col] = bt[col];
    }
    __syncthreads();
    int node = blockIdx.x * blockDim.x + threadIdx.x;
    if (node >= n) return;

    float x[64];
    const float4* hp = reinterpret_cast<const float4*>(c + (size_t)node * 64);
#pragma unroll
    for (int k4 = 0; k4 < 16; k4++) {
        float4 v4 = hp[k4];
        float tmp[4] = {v4.x, v4.y, v4.z, v4.w};
#pragma unroll
        for (int j = 0; j < 4; j++) {
            int k = k4 * 4 + j;
            float v = fmaxf(tmp[j], 0.0f);
            float y = (v - smean[k]) * sscale[k] + sbt[k];
            x[k] = (y > 0.0f) ? y : expm1f(y);
        }
    }

    float t1[32];
#pragma unroll 4
    for (int j = 0; j < 32; j++) {
        float acc = sb1[j];
#pragma unroll
        for (int k = 0; k < 64; k++) acc = fmaf(x[k], sW1[k * 32 + j], acc);
        t1[j] = (acc > 0.0f) ? acc : expm1f(acc);
    }

    float t2[16];
#pragma unroll 4
    for (int j = 0; j < 16; j++) {
        float acc = sb2[j];
#pragma unroll
        for (int k = 0; k < 32; k++) acc = fmaf(t1[k], sW2[k * 16 + j], acc);
        t2[j] = (acc > 0.0f) ? acc : expm1f(acc);
    }

    float o0 = sb3[0], o1 = sb3[1];
#pragma unroll
    for (int k = 0; k < 16; k++) {
        o0 = fmaf(t2[k], sW3[k * 2 + 0], o0);
        o1 = fmaf(t2[k], sW3[k * 2 + 1], o1);
    }
    float m = fmaxf(o0, o1);
    float lse = m + logf(expf(o0 - m) + expf(o1 - m));
    out[node * 2 + 0] = o0 - lse;
    out[node * 2 + 1] = o1 - lse;
}

// ----------------- launch -----------------
extern "C" void kernel_launch(void* const* d_in, const int* in_sizes, int n_in,
                              void* d_out, int out_size) {
    const float* x   = (const float*)d_in[0];
    const int* eidx  = (const int*)d_in[1];
    const float* W1  = (const float*)d_in[2];
    const float* b1  = (const float*)d_in[3];
    const float* g1  = (const float*)d_in[4];
    const float* bt1 = (const float*)d_in[5];
    const float* W2  = (const float*)d_in[6];
    const float* b2  = (const float*)d_in[7];
    const float* g2  = (const float*)d_in[8];
    const float* bt2 = (const float*)d_in[9];
    const float* W3  = (const float*)d_in[10];
    const float* b3  = (const float*)d_in[11];
    const float* g3  = (const float*)d_in[12];
    const float* bt3 = (const float*)d_in[13];
    const float* Wf1 = (const float*)d_in[14];
    const float* bf1 = (const float*)d_in[15];
    const float* Wf2 = (const float*)d_in[16];
    const float* bf2 = (const float*)d_in[17];
    const float* Wf3 = (const float*)d_in[18];
    const float* bf3 = (const float*)d_in[19];
    float* out = (float*)d_out;

    const int n = in_sizes[0] / 4;
    const int e = in_sizes[1] / 2;
    const int* src = eidx;
    const int* dst = eidx + e;

    float *pA, *pB, *pC, *pDinv, *pStats;
    int *pDeg, *pRowptr, *pCursor, *pPartial, *pBlockOff;
    int2* pEdge;
    cudaGetSymbolAddress((void**)&pA, g_A);
    cudaGetSymbolAddress((void**)&pB, g_B);
    cudaGetSymbolAddress((void**)&pC, g_C);
    cudaGetSymbolAddress((void**)&pDinv, g_dinv);
    cudaGetSymbolAddress((void**)&pDeg, g_deg);
    cudaGetSymbolAddress((void**)&pRowptr, g_rowptr);
    cudaGetSymbolAddress((void**)&pCursor, g_cursor);
    cudaGetSymbolAddress((void**)&pEdge, g_edge);
    cudaGetSymbolAddress((void**)&pPartial, g_partial);
    cudaGetSymbolAddress((void**)&pBlockOff, g_blockOff);
    cudaGetSymbolAddress((void**)&pStats, g_stats);
    float* pS0 = pStats;
    float* pS1 = pStats + 128;
    float* pS2 = pStats + 256;

    const int TB = 256;
    const int gn = (n + TB - 1) / TB;   // 391 blocks
    const int ge = (e + TB - 1) / TB;

    // degree / dinv / CSR build
    k_deg_init<<<gn, TB>>>(pDeg, n);
    k_deg_count<<<ge, TB>>>(dst, pDeg, e);
    k_dinv_blocksums<<<gn, TB>>>(pDeg, pDinv, pPartial, n);
    k_scan_partials<<<1, 512>>>(pPartial, pBlockOff, gn);
    k_rowptr<<<gn, TB>>>(pDeg, pBlockOff, pRowptr, pCursor, n);
    k_place<<<ge, TB>>>(src, dst, pDinv, pCursor, pEdge, e);

    // ---- layer 1: gather x (4) -> gemm 4->16 ----
    {
        k_gather<4><<<(n * 1 + TB - 1) / TB, TB>>>(x, pRowptr, pEdge, pDinv, pB, pS0, n);
        k_gemm_stats<4, 16><<<gn, TB>>>(pB, W1, b1, pC, pS0, n);
    }
    // ---- layer 2: bn_elu (16) -> gather (16) -> gemm 16->32 ----
    {
        k_bn_elu<16><<<(n * 16 + TB - 1) / TB, TB>>>(pC, pS0, g1, bt1, pA, n);
        k_gather<16><<<(n * 4 + TB - 1) / TB, TB>>>(pA, pRowptr, pEdge, pDinv, pB, pS1, n);
        k_gemm_stats<16, 32><<<gn, TB>>>(pB, W2, b2, pC, pS1, n);
    }
    // ---- layer 3: bn_elu (32) -> gather (32) -> gemm 32->64 ----
    {
        k_bn_elu<32><<<(n * 32 + TB - 1) / TB, TB>>>(pC, pS1, g2, bt2, pA, n);
        k_gather<32><<<(n * 8 + TB - 1) / TB, TB>>>(pA, pRowptr, pEdge, pDinv, pB, pS2, n);
        k_gemm_stats<32, 64><<<gn, TB>>>(pB, W3, b3, pC, pS2, n);
    }

    // ---- bn_elu of layer3 + MLP head + log_softmax ----
    k_mlp<<<(n + 127) / 128, 128>>>(pC, pS2, g3, bt3, Wf1, bf1, Wf2, bf2, Wf3, bf3, out, n);
}